// round 2
// baseline (speedup 1.0000x reference)
#include <cuda_runtime.h>

// QPChargeNormalization: per batch row b (B=4096 rows):
//   n = 256*16 + 512*8 = 8192
//   c = [c_iso(4096) | c_aniso(4096)],  q = [int_iso | int_aniso]
//   h = (sum(charge[b,:]) - q.c) / (q.q)        (= u/2)
//   x = c + h*q
// Output = [sol_iso flattened (B*4096) | sol_aniso flattened (B*4096)]
//
// One CTA per row, 512 threads, data held in registers between the
// reduction and the axpy so every element moves over HBM exactly once.

#define NTHREADS 512

__device__ __forceinline__ float dot4(float4 a, float4 b) {
    return fmaf(a.x, b.x, fmaf(a.y, b.y, fmaf(a.z, b.z, a.w * b.w)));
}

__device__ __forceinline__ float4 axpy4(float h, float4 q, float4 c) {
    float4 o;
    o.x = fmaf(h, q.x, c.x);
    o.y = fmaf(h, q.y, c.y);
    o.z = fmaf(h, q.z, c.z);
    o.w = fmaf(h, q.w, c.w);
    return o;
}

__global__ void __launch_bounds__(NTHREADS)
qp_charge_norm_kernel(const float4* __restrict__ c_iso,
                      const float4* __restrict__ c_aniso,
                      const float4* __restrict__ q_iso,
                      const float4* __restrict__ q_aniso,
                      const float*  __restrict__ charge,
                      float4*       __restrict__ out,
                      int B)
{
    const int b = blockIdx.x;
    const int t = threadIdx.x;
    const size_t row4 = 1024;              // float4 per 4096-float half-row

    const float4* ci = c_iso   + (size_t)b * row4;
    const float4* ca = c_aniso + (size_t)b * row4;
    const float4* qi = q_iso   + (size_t)b * row4;
    const float4* qa = q_aniso + (size_t)b * row4;

    // 8 x float4 loads per thread, issued back-to-back for MLP.
    float4 c0 = ci[t];
    float4 c1 = ci[t + NTHREADS];
    float4 c2 = ca[t];
    float4 c3 = ca[t + NTHREADS];
    float4 q0 = qi[t];
    float4 q1 = qi[t + NTHREADS];
    float4 q2 = qa[t];
    float4 q3 = qa[t + NTHREADS];

    float Qv = (t < 256) ? charge[(size_t)b * 256 + t] : 0.0f;

    float qc = dot4(q0, c0) + dot4(q1, c1) + dot4(q2, c2) + dot4(q3, c3);
    float qq = dot4(q0, q0) + dot4(q1, q1) + dot4(q2, q2) + dot4(q3, q3);

    // Warp-level tree reduction of (qc, qq, Qv).
    #pragma unroll
    for (int m = 16; m; m >>= 1) {
        qc += __shfl_xor_sync(0xffffffffu, qc, m);
        qq += __shfl_xor_sync(0xffffffffu, qq, m);
        Qv += __shfl_xor_sync(0xffffffffu, Qv, m);
    }

    __shared__ float s_qc[16], s_qq[16], s_Q[16];
    __shared__ float s_h;
    const int wid  = t >> 5;
    const int lane = t & 31;
    if (lane == 0) { s_qc[wid] = qc; s_qq[wid] = qq; s_Q[wid] = Qv; }
    __syncthreads();

    if (wid == 0) {
        float a  = (lane < 16) ? s_qc[lane] : 0.0f;
        float g  = (lane < 16) ? s_qq[lane] : 0.0f;
        float qs = (lane < 16) ? s_Q[lane]  : 0.0f;
        #pragma unroll
        for (int m = 8; m; m >>= 1) {
            a  += __shfl_xor_sync(0xffffffffu, a,  m);
            g  += __shfl_xor_sync(0xffffffffu, g,  m);
            qs += __shfl_xor_sync(0xffffffffu, qs, m);
        }
        if (lane == 0) s_h = (qs - a) / g;   // h = u/2 = (Q - q.c)/(q.q)
    }
    __syncthreads();

    const float h = s_h;

    float4* oi = out + (size_t)b * row4;                      // iso block
    float4* oa = out + (size_t)B * row4 + (size_t)b * row4;   // aniso block

    oi[t]            = axpy4(h, q0, c0);
    oi[t + NTHREADS] = axpy4(h, q1, c1);
    oa[t]            = axpy4(h, q2, c2);
    oa[t + NTHREADS] = axpy4(h, q3, c3);
}

extern "C" void kernel_launch(void* const* d_in, const int* in_sizes, int n_in,
                              void* d_out, int out_size)
{
    const float4* c_iso   = (const float4*)d_in[0];
    const float4* c_aniso = (const float4*)d_in[1];
    const float4* q_iso   = (const float4*)d_in[2];
    const float4* q_aniso = (const float4*)d_in[3];
    const float*  charge  = (const float*) d_in[4];
    float4*       out     = (float4*)d_out;

    const int B = in_sizes[4] / 256;   // charge is [B, 256]

    qp_charge_norm_kernel<<<B, NTHREADS>>>(c_iso, c_aniso, q_iso, q_aniso,
                                           charge, out, B);
}